// round 4
// baseline (speedup 1.0000x reference)
#include <cuda_runtime.h>
#include <cuda_bf16.h>

// P1 FEM evaluation on a structured 17x17 grid over [0,1]^2.
// Direct cell lookup replaces the reference's 512-triangle scan.
//
// Bitwise-faithful decision logic vs the JAX reference:
//  - Minv entries are exactly {+-16, 0}; multiplying by 16 is an exact
//    exponent shift in fp32, so (ux - fx) == 16*fl(X - xs[i]) bit-exactly
//    and all s/t values match the reference matmul results bit-exactly.
//  - TOL = 1e-10 is below fp32 ulp everywhere relevant:
//      * interior grid-line points fail every (strict) bbox test in the
//        reference -> output stays 0  (handled via the `dead` flag)
//      * x==0 / y==0 edges pass (bbox lower bound becomes -1e-10)
//  - scan order = all lower triangles then all upper -> upper wins on the
//    shared diagonal (values are bitwise identical there anyway).

static constexpr int   NPTS  = 8 * 262144;     // 2,097,152 points
static constexpr float TOLF  = 1e-10f;

__device__ __forceinline__ float eval_point(float X, float Y,
                                            const float* __restrict__ ws) {
    float ux = X * 16.0f;              // exact (power-of-2 scale)
    float uy = Y * 16.0f;
    float fx = floorf(ux);
    float fy = floorf(uy);
    // Interior grid line -> reference's strict bbox test fails everywhere.
    bool dead = ((ux == fx) && (fx != 0.0f)) || ((uy == fy) && (fy != 0.0f));
    fx = fminf(fx, 15.0f);             // defensive clamp (X,Y in [0,1))
    fy = fminf(fy, 15.0f);
    int i = (int)fx;
    int j = (int)fy;

    float dx16 = ux - fx;              // == 16 * fl(X - xs[i]) exactly
    float dy16 = uy - fy;              // == 16 * fl(Y - xs[j]) exactly

    // Lower triangle (v00, v10, v11):  s=(dx-dy)*16, t=dy*16
    float sl = dx16 - dy16;
    float tl = dy16;
    // Upper triangle (v00, v11, v01):  s=dx*16, t=(dy-dx)*16
    float su = dx16;
    float tu = dy16 - dx16;

    int v00 = i * 17 + j;              // coords are (xs[i], xs[j]), vid = i*17+j
    float w00 = ws[v00];
    float w01 = ws[v00 + 1];           // v01 = vid[i, j+1]
    float w10 = ws[v00 + 17];          // v10 = vid[i+1, j]
    float w11 = ws[v00 + 18];          // v11 = vid[i+1, j+1]

    float val = 0.0f;
    if ((sl > -TOLF) && (tl > -TOLF) && ((sl + tl) < 1.0f))
        val = (1.0f - sl - tl) * w00 + sl * w10 + tl * w11;
    if ((su > -TOLF) && (tu > -TOLF) && ((su + tu) < 1.0f))
        val = (1.0f - su - tu) * w00 + su * w11 + tu * w01;   // upper overrides (scan order)
    return dead ? 0.0f : val;
}

__global__ void __launch_bounds__(256)
p1_eval_kernel(const float4* __restrict__ x4,
               const float*  __restrict__ w,
               float2*       __restrict__ out2) {
    __shared__ float ws[289];
    for (int t = threadIdx.x; t < 289; t += 256) ws[t] = w[t];
    __syncthreads();

    int base = blockIdx.x * (256 * 4) + threadIdx.x;
    #pragma unroll
    for (int k = 0; k < 4; k++) {
        int idx = base + k * 256;      // coalesced float4 (2 points each)
        float4 v = x4[idx];
        float2 r;
        r.x = eval_point(v.x, v.y, ws);
        r.y = eval_point(v.z, v.w, ws);
        out2[idx] = r;                 // coalesced float2 stores
    }
}

extern "C" void kernel_launch(void* const* d_in, const int* in_sizes, int n_in,
                              void* d_out, int out_size) {
    // Identify inputs robustly by element count:
    //   x: 4,194,304 floats (largest), weight: 289 floats.
    const float* x = nullptr;
    const float* w = nullptr;
    int max_sz = -1;
    for (int k = 0; k < n_in; k++) {
        if (in_sizes[k] == 289) w = (const float*)d_in[k];
        if (in_sizes[k] > max_sz) { max_sz = in_sizes[k]; x = (const float*)d_in[k]; }
    }

    // 2,097,152 points -> 1,048,576 float4s -> 1024 blocks x 256 threads x 4.
    const int threads = 256;
    const int f4_per_thread = 4;
    const int n_f4 = NPTS / 2;
    const int blocks = n_f4 / (threads * f4_per_thread);   // = 1024 exactly

    p1_eval_kernel<<<blocks, threads>>>((const float4*)x, w, (float2*)d_out);
}